// round 1
// baseline (speedup 1.0000x reference)
#include <cuda_runtime.h>

typedef unsigned long long u64;

#define KN 1000000
#define KV 200000

// ---------------- scratch (static __device__, no allocation) ----------------
static __device__ float g_pf[(size_t)32*KN];       // point features, col-major [32][N]
static __device__ float g_vox[(size_t)32*KV];      // voxel max,      col-major [32][V]
static __device__ float g_t[(size_t)KV*64];        // vf @ fu_w_top,  row-major [V][64]
static __device__ float g_fused[(size_t)64*KN];    // fused feats,    col-major [64][N]
static __device__ int   g_pvi[KN];
static __device__ unsigned char g_bidv[KN];
static __device__ float g_bsum[256];
static __device__ float g_bcnt[4];
static __device__ float g_gsc[256];                // 1 + gate, [B][64]
static __device__ int   g_ids32 = 0;               // 1 if ids buffer is int32

// ---------------- f32x2 packed helpers ----------------
__device__ __forceinline__ u64 pk2(float lo, float hi){ u64 r; asm("mov.b64 %0,{%1,%2};" : "=l"(r) : "f"(lo), "f"(hi)); return r; }
__device__ __forceinline__ void up2(u64 v, float& lo, float& hi){ asm("mov.b64 {%0,%1},%2;" : "=f"(lo), "=f"(hi) : "l"(v)); }
__device__ __forceinline__ u64 ffma2(u64 a, u64 b, u64 c){ u64 d; asm("fma.rn.f32x2 %0,%1,%2,%3;" : "=l"(d) : "l"(a), "l"(b), "l"(c)); return d; }
__device__ __forceinline__ u64 fadd2(u64 a, u64 b){ u64 d; asm("add.rn.f32x2 %0,%1,%2;" : "=l"(d) : "l"(a), "l"(b)); return d; }

#define RS_BN 0.9999950000374997f   // 1/sqrt(1+1e-5)

// ---------------- K0: zero accumulators + detect id dtype ----------------
__global__ void __launch_bounds__(256) k0_init(const void* __restrict__ ids, int N, int V){
  int i = blockIdx.x*blockDim.x + threadIdx.x;
  if (i < 32*V) g_vox[i] = 0.f;
  if (i < 256)  g_bsum[i] = 0.f;
  if (i < 4)    g_bcnt[i] = 0.f;
  if (i < 4096 && 2*i+1 < N){
    long long v = ((const long long*)ids)[i];
    if ((unsigned long long)v >= (unsigned long long)V) g_ids32 = 1;  // monotonic, deterministic
  }
}

// ---------------- K1: point encoder 4->32->64->32 + atomic segment max ----------------
__global__ void __launch_bounds__(256) k1_point(
    const float* __restrict__ pts, const void* __restrict__ ids,
    const float* __restrict__ w1, const float* __restrict__ gg1, const float* __restrict__ bb1,
    const float* __restrict__ w2, const float* __restrict__ gg2, const float* __restrict__ bb2,
    const float* __restrict__ w3, const float* __restrict__ gg3, const float* __restrict__ bb3,
    int N, int V)
{
  __shared__ __align__(16) float sw1[128];
  __shared__ __align__(16) float sw2[2048];
  __shared__ __align__(16) float sw3[2048];
  __shared__ float ss1[32], sb1[32], ss2[64], sb2[64], ss3[32], sb3[32];
  int t = threadIdx.x;
  for (int i=t;i<128;i+=256) sw1[i]=w1[i];
  for (int i=t;i<2048;i+=256){ sw2[i]=w2[i]; sw3[i]=w3[i]; }
  if (t<32){ ss1[t]=gg1[t]*RS_BN; sb1[t]=bb1[t]; ss3[t]=gg3[t]*RS_BN; sb3[t]=bb3[t]; }
  if (t<64){ ss2[t]=gg2[t]*RS_BN; sb2[t]=bb2[t]; }
  __syncthreads();
  int p = blockIdx.x*256 + t;
  if (p >= N) return;

  const float* pr = pts + (size_t)p*5;
  float bidf = pr[0];
  float c0=pr[1], c1=pr[2], c2=pr[3], c3=pr[4];
  int bid = (int)bidf;
  g_bidv[p] = (unsigned char)bid;
  int vid;
  if (g_ids32) vid = ((const int*)ids)[p];
  else         vid = (int)((const long long*)ids)[p];
  g_pvi[p] = vid;

  float h1[32];
#pragma unroll
  for (int o=0;o<32;o++){
    float a = c0*sw1[o] + c1*sw1[32+o] + c2*sw1[64+o] + c3*sw1[96+o];
    h1[o] = fmaxf(ss1[o]*a + sb1[o], 0.f);
  }

  u64 h3[16];
#pragma unroll
  for (int k=0;k<16;k++) h3[k]=0ull;
  const u64* W2 = (const u64*)sw2;   // [32][32] pairs
  const u64* W3 = (const u64*)sw3;   // [64][16] pairs
#pragma unroll 1
  for (int c=0;c<4;c++){             // layer2 outputs in chunks of 16
    u64 acc[8];
#pragma unroll
    for (int j=0;j<8;j++) acc[j]=0ull;
#pragma unroll
    for (int i=0;i<32;i++){
      u64 xb = pk2(h1[i],h1[i]);
      const u64* wr = W2 + i*32 + c*8;
#pragma unroll
      for (int j=0;j<8;j++) acc[j]=ffma2(xb, wr[j], acc[j]);
    }
#pragma unroll
    for (int j=0;j<8;j++){
      float a0,a1; up2(acc[j],a0,a1);
      int o = c*16 + 2*j;
      float v0 = fmaxf(ss2[o]*a0 + sb2[o], 0.f);
      float v1 = fmaxf(ss2[o+1]*a1 + sb2[o+1], 0.f);
      u64 x0 = pk2(v0,v0), x1 = pk2(v1,v1);
      const u64* w3a = W3 + o*16;
      const u64* w3b = W3 + (o+1)*16;
#pragma unroll
      for (int k=0;k<16;k++) h3[k]=ffma2(x0, w3a[k], h3[k]);
#pragma unroll
      for (int k=0;k<16;k++) h3[k]=ffma2(x1, w3b[k], h3[k]);
    }
  }
#pragma unroll
  for (int k=0;k<16;k++){
    float d0,d1; up2(h3[k],d0,d1);
    int o = 2*k;
    float r0 = fmaxf(ss3[o]*d0 + sb3[o], 0.f);
    float r1 = fmaxf(ss3[o+1]*d1 + sb3[o+1], 0.f);
    g_pf[(size_t)o*N + p]     = r0;
    g_pf[(size_t)(o+1)*N + p] = r1;
    // pf >= 0 so int-bitpattern atomicMax over a 0-initialized buffer == segment_max + isfinite->0
    atomicMax((int*)&g_vox[(size_t)o*V + vid],     __float_as_int(r0));
    atomicMax((int*)&g_vox[(size_t)(o+1)*V + vid], __float_as_int(r1));
  }
}

// ---------------- K2: voxel MLP + aux head + precompute t = vf @ fu_w_top ----------------
__global__ void __launch_bounds__(256) k2_voxel(
  const float* __restrict__ vw1, const float* __restrict__ vg1, const float* __restrict__ vb1,
  const float* __restrict__ vw2, const float* __restrict__ vg2, const float* __restrict__ vb2,
  const float* __restrict__ aw1, const float* __restrict__ ag1, const float* __restrict__ ab1,
  const float* __restrict__ aw2,
  const float* __restrict__ fuw,
  float* __restrict__ aux, int V, int N)
{
  __shared__ __align__(16) float s_vw1[1024], s_vw2[1024], s_aw1[1024], s_aw2[640], s_fut[2048];
  __shared__ float s_vs1[32], s_vb1[32], s_vs2[32], s_vb2[32], s_as1[32], s_ab1[32];
  int t = threadIdx.x;
  for (int i=t;i<1024;i+=256){ s_vw1[i]=vw1[i]; s_vw2[i]=vw2[i]; s_aw1[i]=aw1[i]; }
  for (int i=t;i<640;i+=256)  s_aw2[i]=aw2[i];
  for (int i=t;i<2048;i+=256) s_fut[i]=fuw[i];       // fu_w rows 0..31 (the pvf half)
  if (t<32){ s_vs1[t]=vg1[t]*RS_BN; s_vb1[t]=vb1[t];
             s_vs2[t]=vg2[t]*RS_BN; s_vb2[t]=vb2[t];
             s_as1[t]=ag1[t]*RS_BN; s_ab1[t]=ab1[t]; }
  __syncthreads();
  int v = blockIdx.x*256 + t;
  if (v >= V) return;
  const u64* W1  = (const u64*)s_vw1;
  const u64* W2v = (const u64*)s_vw2;
  const u64* WA1 = (const u64*)s_aw1;
  const u64* WA2 = (const u64*)s_aw2;
  const u64* WT  = (const u64*)s_fut;

  float x[32];
#pragma unroll
  for (int i=0;i<32;i++) x[i] = g_vox[(size_t)i*V + v];

  float v1[32];
  {
    u64 acc[16];
#pragma unroll
    for (int j=0;j<16;j++) acc[j]=0ull;
#pragma unroll
    for (int i=0;i<32;i++){
      u64 xb = pk2(x[i],x[i]);
#pragma unroll
      for (int j=0;j<16;j++) acc[j]=ffma2(xb, W1[i*16+j], acc[j]);
    }
#pragma unroll
    for (int j=0;j<16;j++){
      float a0,a1; up2(acc[j],a0,a1);
      v1[2*j]   = fmaxf(s_vs1[2*j]*a0   + s_vb1[2*j],   0.f);
      v1[2*j+1] = fmaxf(s_vs1[2*j+1]*a1 + s_vb1[2*j+1], 0.f);
    }
  }
  // aux head: relu(bn(v1 @ aux_w1)) @ aux_w2
  {
    float a1v[32];
    u64 acc[16];
#pragma unroll
    for (int j=0;j<16;j++) acc[j]=0ull;
#pragma unroll
    for (int i=0;i<32;i++){
      u64 xb = pk2(v1[i],v1[i]);
#pragma unroll
      for (int j=0;j<16;j++) acc[j]=ffma2(xb, WA1[i*16+j], acc[j]);
    }
#pragma unroll
    for (int j=0;j<16;j++){
      float a0,a1; up2(acc[j],a0,a1);
      a1v[2*j]   = fmaxf(s_as1[2*j]*a0   + s_ab1[2*j],   0.f);
      a1v[2*j+1] = fmaxf(s_as1[2*j+1]*a1 + s_ab1[2*j+1], 0.f);
    }
    u64 ao[10];
#pragma unroll
    for (int j=0;j<10;j++) ao[j]=0ull;
#pragma unroll
    for (int i=0;i<32;i++){
      u64 xb = pk2(a1v[i],a1v[i]);
#pragma unroll
      for (int j=0;j<10;j++) ao[j]=ffma2(xb, WA2[i*10+j], ao[j]);
    }
    u64* ap = (u64*)(aux + (size_t)v*20);   // 8B aligned: 80*v bytes
#pragma unroll
    for (int j=0;j<10;j++) ap[j]=ao[j];
  }
  // vf
  float vf[32];
  {
    u64 acc[16];
#pragma unroll
    for (int j=0;j<16;j++) acc[j]=0ull;
#pragma unroll
    for (int i=0;i<32;i++){
      u64 xb = pk2(v1[i],v1[i]);
#pragma unroll
      for (int j=0;j<16;j++) acc[j]=ffma2(xb, W2v[i*16+j], acc[j]);
    }
#pragma unroll
    for (int j=0;j<16;j++){
      float a0,a1; up2(acc[j],a0,a1);
      vf[2*j]   = fmaxf(s_vs2[2*j]*a0   + s_vb2[2*j],   0.f);
      vf[2*j+1] = fmaxf(s_vs2[2*j+1]*a1 + s_vb2[2*j+1], 0.f);
    }
  }
  // t = vf @ fu_w_top  (row-major [V][64] for contiguous per-point gathers)
#pragma unroll 1
  for (int h=0;h<2;h++){
    u64 tc[16];
#pragma unroll
    for (int j=0;j<16;j++) tc[j]=0ull;
#pragma unroll
    for (int i=0;i<32;i++){
      u64 xb = pk2(vf[i],vf[i]);
#pragma unroll
      for (int j=0;j<16;j++) tc[j]=ffma2(xb, WT[i*32 + h*16 + j], tc[j]);
    }
    u64* tp = (u64*)g_t + (size_t)v*32 + h*16;
#pragma unroll
    for (int j=0;j<16;j++) tp[j]=tc[j];
  }
}

// ---------------- K3: fused = relu(bn(t[pv] + pf @ fu_w_bot)) ; batch sums ----------------
__global__ void __launch_bounds__(256) k3_fuse(
  const float* __restrict__ fuw, const float* __restrict__ fug, const float* __restrict__ fub,
  int N)
{
  __shared__ __align__(16) float s_bot[2048];
  __shared__ float s_s[64], s_b[64];
  __shared__ float s_sum[256];
  __shared__ float s_cnt[4];
  int t = threadIdx.x;
  for (int i=t;i<2048;i+=256) s_bot[i]=fuw[2048+i];   // fu_w rows 32..63 (the pf half)
  if (t<64){ s_s[t]=fug[t]*RS_BN; s_b[t]=fub[t]; }
  if (t<256) s_sum[t]=0.f;
  if (t<4)   s_cnt[t]=0.f;
  __syncthreads();
  const u64* WB = (const u64*)s_bot;
  int T = gridDim.x*blockDim.x;
  int iters = (N + T - 1)/T;
  int lane = t & 31;
  for (int it=0; it<iters; it++){
    int p = blockIdx.x*blockDim.x + t + it*T;
    bool valid = p < N;
    int pc = valid ? p : N-1;
    int bid = g_bidv[pc];
    int vid = g_pvi[pc];
    const u64* trow = (const u64*)g_t + (size_t)vid*32;
    u64 f[32];
#pragma unroll
    for (int k=0;k<32;k++) f[k]=trow[k];
#pragma unroll 4
    for (int i=0;i<32;i++){
      float xv = g_pf[(size_t)i*N + pc];
      u64 xb = pk2(xv,xv);
#pragma unroll
      for (int k=0;k<32;k++) f[k]=ffma2(xb, WB[i*32+k], f[k]);
    }
#pragma unroll
    for (int k=0;k<32;k++){
      float a0,a1; up2(f[k],a0,a1);
      int o=2*k;
      float r0 = fmaxf(s_s[o]*a0   + s_b[o],   0.f);
      float r1 = fmaxf(s_s[o+1]*a1 + s_b[o+1], 0.f);
      if (valid){
        g_fused[(size_t)o*N + p]     = r0;
        g_fused[(size_t)(o+1)*N + p] = r1;
      }
      f[k] = valid ? pk2(r0,r1) : 0ull;
    }
    const unsigned FULL = 0xffffffffu;
    unsigned vb = __ballot_sync(FULL, valid);
    int b0 = __shfl_sync(FULL, bid, 0);
    bool uni = __all_sync(FULL, (!valid) || (bid==b0));
    if (uni){
#pragma unroll
      for (int k=0;k<32;k++){
        u64 vv = f[k];
        vv = fadd2(vv, __shfl_xor_sync(FULL, vv, 16));
        vv = fadd2(vv, __shfl_xor_sync(FULL, vv, 8));
        vv = fadd2(vv, __shfl_xor_sync(FULL, vv, 4));
        vv = fadd2(vv, __shfl_xor_sync(FULL, vv, 2));
        vv = fadd2(vv, __shfl_xor_sync(FULL, vv, 1));
        f[k]=vv;
      }
      if (lane==0){
        float* bs = &s_sum[b0*64];
#pragma unroll
        for (int k=0;k<32;k++){
          float a0,a1; up2(f[k],a0,a1);
          atomicAdd(&bs[2*k],   a0);
          atomicAdd(&bs[2*k+1], a1);
        }
        atomicAdd(&s_cnt[b0], (float)__popc(vb));
      }
    } else if (valid){
      float* bs = &s_sum[bid*64];
#pragma unroll
      for (int k=0;k<32;k++){
        float a0,a1; up2(f[k],a0,a1);
        atomicAdd(&bs[2*k],   a0);
        atomicAdd(&bs[2*k+1], a1);
      }
      atomicAdd(&s_cnt[bid], 1.f);
    }
  }
  __syncthreads();
  if (t < 256) atomicAdd(&g_bsum[t], s_sum[t]);
  if (t < 4)   atomicAdd(&g_bcnt[t], s_cnt[t]);
}

// ---------------- K4: SE gate (tiny) ----------------
__global__ void __launch_bounds__(256) k4_gate(
  const float* __restrict__ sw1, const float* __restrict__ sb1,
  const float* __restrict__ sw2, const float* __restrict__ sb2)
{
  __shared__ float sm[256];
  __shared__ float sh[16];
  int t = threadIdx.x;
  int b = t>>6, o = t&63;
  float m = g_bsum[t] / fmaxf(g_bcnt[b], 1.f);
  sm[t] = m;
  __syncthreads();
  if (t < 16){
    int bb = t>>2, j = t&3;
    float a = sb1[j];
    for (int i=0;i<64;i++) a += sm[bb*64+i]*sw1[i*4+j];
    sh[t] = fmaxf(a, 0.f);
  }
  __syncthreads();
  float a = sb2[o];
#pragma unroll
  for (int j=0;j<4;j++) a += sh[b*4+j]*sw2[j*64+o];
  g_gsc[t] = 1.f + 1.f/(1.f + expf(-a));
}

// ---------------- K5: classification head ----------------
__global__ void __launch_bounds__(256) k5_head(
  const float* __restrict__ cw1, const float* __restrict__ cg1, const float* __restrict__ cb1,
  const float* __restrict__ cw2,
  float* __restrict__ out, int N)
{
  __shared__ __align__(16) float s_w1[2048];
  __shared__ __align__(16) float s_w2[640];
  __shared__ float s_s[32], s_b[32];
  __shared__ float s_g[256];
  int t = threadIdx.x;
  for (int i=t;i<2048;i+=256) s_w1[i]=cw1[i];
  for (int i=t;i<640;i+=256)  s_w2[i]=cw2[i];
  if (t<32){ s_s[t]=cg1[t]*RS_BN; s_b[t]=cb1[t]; }
  s_g[t] = g_gsc[t];
  __syncthreads();
  int p = blockIdx.x*256 + t;
  if (p >= N) return;
  int bid = g_bidv[p];
  const float* gl = &s_g[bid*64];
  const u64* W1 = (const u64*)s_w1;
  const u64* W2 = (const u64*)s_w2;
  u64 acc[16];
#pragma unroll
  for (int j=0;j<16;j++) acc[j]=0ull;
#pragma unroll 2
  for (int k=0;k<32;k++){
    int i0 = 2*k, i1 = 2*k+1;
    float f0 = g_fused[(size_t)i0*N + p] * gl[i0];
    float f1 = g_fused[(size_t)i1*N + p] * gl[i1];
    u64 x0 = pk2(f0,f0), x1 = pk2(f1,f1);
    const u64* wa = W1 + i0*16;
    const u64* wb = W1 + i1*16;
#pragma unroll
    for (int j=0;j<16;j++) acc[j]=ffma2(x0, wa[j], acc[j]);
#pragma unroll
    for (int j=0;j<16;j++) acc[j]=ffma2(x1, wb[j], acc[j]);
  }
  float h[32];
#pragma unroll
  for (int j=0;j<16;j++){
    float a0,a1; up2(acc[j],a0,a1);
    h[2*j]   = fmaxf(s_s[2*j]*a0   + s_b[2*j],   0.f);
    h[2*j+1] = fmaxf(s_s[2*j+1]*a1 + s_b[2*j+1], 0.f);
  }
  u64 ov[10];
#pragma unroll
  for (int j=0;j<10;j++) ov[j]=0ull;
#pragma unroll
  for (int i=0;i<32;i++){
    u64 xb = pk2(h[i],h[i]);
#pragma unroll
    for (int j=0;j<10;j++) ov[j]=ffma2(xb, W2[i*10+j], ov[j]);
  }
  u64* op = (u64*)(out + (size_t)p*20);  // 80*p bytes -> 8B aligned
#pragma unroll
  for (int j=0;j<10;j++) op[j]=ov[j];
}

// ---------------- launcher ----------------
extern "C" void kernel_launch(void* const* d_in, const int* in_sizes, int n_in,
                              void* d_out, int out_size)
{
  const float* points = (const float*)d_in[0];
  const void*  ids    = d_in[1];
  const float* pe_w1=(const float*)d_in[2],  *pe_g1=(const float*)d_in[3],  *pe_b1=(const float*)d_in[4];
  const float* pe_w2=(const float*)d_in[5],  *pe_g2=(const float*)d_in[6],  *pe_b2=(const float*)d_in[7];
  const float* pe_w3=(const float*)d_in[8],  *pe_g3=(const float*)d_in[9],  *pe_b3=(const float*)d_in[10];
  const float* ve_w1=(const float*)d_in[11], *ve_g1=(const float*)d_in[12], *ve_b1=(const float*)d_in[13];
  const float* ve_w2=(const float*)d_in[14], *ve_g2=(const float*)d_in[15], *ve_b2=(const float*)d_in[16];
  const float* fu_w =(const float*)d_in[17], *fu_g =(const float*)d_in[18], *fu_b =(const float*)d_in[19];
  const float* se_w1=(const float*)d_in[20], *se_b1=(const float*)d_in[21];
  const float* se_w2=(const float*)d_in[22], *se_b2=(const float*)d_in[23];
  const float* cl_w1=(const float*)d_in[24], *cl_g1=(const float*)d_in[25], *cl_b1=(const float*)d_in[26];
  const float* cl_w2=(const float*)d_in[27];
  const float* au_w1=(const float*)d_in[28], *au_g1=(const float*)d_in[29], *au_b1=(const float*)d_in[30];
  const float* au_w2=(const float*)d_in[31];

  int N = in_sizes[0] / 5;
  int V = (out_size - N*20) / 20;
  float* out = (float*)d_out;
  float* aux = out + (size_t)N*20;

  int nb0 = (32*V + 255)/256;
  k0_init<<<nb0, 256>>>(ids, N, V);
  k1_point<<<(N+255)/256, 256>>>(points, ids,
      pe_w1, pe_g1, pe_b1, pe_w2, pe_g2, pe_b2, pe_w3, pe_g3, pe_b3, N, V);
  k2_voxel<<<(V+255)/256, 256>>>(ve_w1, ve_g1, ve_b1, ve_w2, ve_g2, ve_b2,
      au_w1, au_g1, au_b1, au_w2, fu_w, aux, V, N);
  k3_fuse<<<2048, 256>>>(fu_w, fu_g, fu_b, N);
  k4_gate<<<1, 256>>>(se_w1, se_b1, se_w2, se_b2);
  k5_head<<<(N+255)/256, 256>>>(cl_w1, cl_g1, cl_b1, cl_w2, out, N);
}